// round 2
// baseline (speedup 1.0000x reference)
#include <cuda_runtime.h>
#include <math.h>

// ---------------- problem constants ----------------
#define NCTA 148
#define NTHR 256
#define WPC  8                  // warps per CTA
#define NWRP (NCTA * WPC)       // 1184 warps grid-wide

#define Mm   10
#define Nn   10
#define TT   100
#define H1   1600
#define H2   400
#define HID  2000
#define DIN  30
#define DOUT 100

// ---------------- global scratch (no allocation allowed) ----------------
__device__ float g_a[H1];
__device__ float g_h1[2][HID];
__device__ float g_h2[2][HID];
__device__ float g_g[H2];

// software grid barrier state
__device__ unsigned g_count;
__device__ volatile unsigned g_gen;

// All 148 CTAs are guaranteed co-resident (1 CTA/SM, 148 <= 152 SMs on GB300),
// so a spin barrier cannot deadlock.
__device__ __forceinline__ void grid_sync() {
    __threadfence();          // make this thread's global writes visible
    __syncthreads();          // whole CTA arrived
    if (threadIdx.x == 0) {
        unsigned gen = g_gen;
        if (atomicAdd(&g_count, 1u) == (unsigned)gridDim.x - 1u) {
            g_count = 0u;
            __threadfence();
            g_gen = gen + 1u; // release
        } else {
            while (g_gen == gen) { __nanosleep(32); }
        }
        __threadfence();      // acquire
    }
    __syncthreads();
}

__device__ __forceinline__ float wred(float v) {
    v += __shfl_xor_sync(0xffffffffu, v, 16);
    v += __shfl_xor_sync(0xffffffffu, v, 8);
    v += __shfl_xor_sync(0xffffffffu, v, 4);
    v += __shfl_xor_sync(0xffffffffu, v, 2);
    v += __shfl_xor_sync(0xffffffffu, v, 1);
    return v;
}

__device__ __forceinline__ float sigmoidf_(float x) {
    return 1.0f / (1.0f + expf(-x));
}

// One GRU layer: warp-per-hidden-unit. For unit j we need rows j, j+HID,
// j+2HID of both Wi (width KX) and Wh (width HID). Activation float4 is
// loaded once and reused across the 3 gate rows.
template<int KX>
__device__ __forceinline__ void gru_phase(
    const float* __restrict__ Wi, const float* __restrict__ Wh,
    const float* __restrict__ bi, const float* __restrict__ bh,
    const float* __restrict__ x,       // input, length KX
    const float* __restrict__ hprev,   // length HID
    float* __restrict__ hnew,          // length HID
    int gwarp, int lane)
{
    const float4* x4 = (const float4*)x;
    const float4* h4 = (const float4*)hprev;
    for (int j = gwarp; j < HID; j += NWRP) {
        const float4* wir = (const float4*)(Wi + (size_t)j * KX);
        const float4* wiz = (const float4*)(Wi + ((size_t)j + HID) * KX);
        const float4* win = (const float4*)(Wi + ((size_t)j + 2 * HID) * KX);
        const float4* whr = (const float4*)(Wh + (size_t)j * HID);
        const float4* whz = (const float4*)(Wh + ((size_t)j + HID) * HID);
        const float4* whn = (const float4*)(Wh + ((size_t)j + 2 * HID) * HID);

        float air = 0.f, aiz = 0.f, ain = 0.f;
        #pragma unroll 4
        for (int k = lane; k < KX / 4; k += 32) {
            float4 xv = x4[k];
            float4 wr = wir[k], wz = wiz[k], wn = win[k];
            air += wr.x * xv.x + wr.y * xv.y + wr.z * xv.z + wr.w * xv.w;
            aiz += wz.x * xv.x + wz.y * xv.y + wz.z * xv.z + wz.w * xv.w;
            ain += wn.x * xv.x + wn.y * xv.y + wn.z * xv.z + wn.w * xv.w;
        }
        float ahr = 0.f, ahz = 0.f, ahn = 0.f;
        #pragma unroll 4
        for (int k = lane; k < HID / 4; k += 32) {
            float4 hv = h4[k];
            float4 wr = whr[k], wz = whz[k], wn = whn[k];
            ahr += wr.x * hv.x + wr.y * hv.y + wr.z * hv.z + wr.w * hv.w;
            ahz += wz.x * hv.x + wz.y * hv.y + wz.z * hv.z + wz.w * hv.w;
            ahn += wn.x * hv.x + wn.y * hv.y + wn.z * hv.z + wn.w * hv.w;
        }
        air = wred(air); aiz = wred(aiz); ain = wred(ain);
        ahr = wred(ahr); ahz = wred(ahz); ahn = wred(ahn);

        if (lane == 0) {
            float rr = sigmoidf_(air + bi[j]          + ahr + bh[j]);
            float zz = sigmoidf_(aiz + bi[j + HID]    + ahz + bh[j + HID]);
            float nn = tanhf    (ain + bi[j + 2*HID]  + rr * (ahn + bh[j + 2*HID]));
            hnew[j] = (1.0f - zz) * nn + zz * hprev[j];
        }
    }
}

__global__ void __launch_bounds__(NTHR, 1) knet_kernel(
    const float* __restrict__ y,    const float* __restrict__ m1x_0,
    const float* __restrict__ F,    const float* __restrict__ Hm,
    const float* __restrict__ h0,
    const float* __restrict__ W1,   const float* __restrict__ b1,
    const float* __restrict__ Wi0,  const float* __restrict__ Wh0,
    const float* __restrict__ bi0,  const float* __restrict__ bh0,
    const float* __restrict__ Wi1,  const float* __restrict__ Wh1,
    const float* __restrict__ bi1,  const float* __restrict__ bh1,
    const float* __restrict__ W2,   const float* __restrict__ b2,
    const float* __restrict__ W3,   const float* __restrict__ b3,
    float* __restrict__ out)
{
    // Per-CTA redundant copy of the tiny Kalman state (identical in every CTA).
    __shared__ float s_post[Mm], s_prevpost[Mm], s_prevprior[Mm], s_yprev[Nn];
    __shared__ float s_prior[Mm], s_dy[Nn], s_np[Mm];
    __shared__ float s_diff[32], s_inv[4], s_kin[32];
    __shared__ float s_KG[DOUT];
    __shared__ float s_g[H2];
    extern __shared__ float W3s[];   // 100*400 floats = 160 KB, loaded once

    const int tid   = threadIdx.x;
    const int lane  = tid & 31;
    const int warp  = tid >> 5;
    const int gwarp = blockIdx.x * WPC + warp;
    const int gtid  = blockIdx.x * NTHR + tid;

    // ------------- init -------------
    for (int i = gtid; i < HID; i += NCTA * NTHR) {
        g_h1[0][i] = h0[i];
        g_h2[0][i] = h0[HID + i];
    }
    for (int i = tid; i < DOUT * H2; i += NTHR) W3s[i] = W3[i];
    if (tid < Mm) {
        float v = m1x_0[tid];
        s_post[tid] = v; s_prevpost[tid] = 0.0f; s_prevprior[tid] = v;
    }
    __syncthreads();
    if (tid < Mm) {   // tmp = F @ m1x_0
        float pr = 0.f;
        #pragma unroll
        for (int j = 0; j < Mm; j++) pr += F[tid * Mm + j] * s_post[j];
        s_prior[tid] = pr;
    }
    __syncthreads();
    if (tid < Nn) {   // y_prev0 = Hm @ tmp
        float v = 0.f;
        #pragma unroll
        for (int j = 0; j < Mm; j++) v += Hm[tid * Mm + j] * s_prior[j];
        s_yprev[tid] = v;
    }
    grid_sync();

    // ------------- time loop (t==TT is the epilogue that finalizes step T-1) -------------
    for (int t = 0; t <= TT; t++) {
        if (t > 0) {
            // finalize previous step: KG = W3 @ g + b3, new_post = prior + KG @ dy
            for (int i = tid; i < H2; i += NTHR) s_g[i] = g_g[i];
            __syncthreads();
            for (int r = warp; r < DOUT; r += WPC) {
                float acc = 0.f;
                for (int k = lane; k < H2; k += 32) acc += W3s[r * H2 + k] * s_g[k];
                acc = wred(acc);
                if (lane == 0) s_KG[r] = acc + b3[r];
            }
            __syncthreads();
            if (tid < Mm) {
                float np = s_prior[tid];
                #pragma unroll
                for (int j = 0; j < Nn; j++) np += s_KG[tid * Nn + j] * s_dy[j];
                s_np[tid] = np;
                if (blockIdx.x == 0) out[tid * TT + (t - 1)] = np;
            }
            __syncthreads();
            if (tid < Mm) {
                s_prevpost[tid]  = s_post[tid];
                s_prevprior[tid] = s_prior[tid];
                s_post[tid]      = s_np[tid];
                s_yprev[tid]     = y[tid * TT + (t - 1)];
            }
            __syncthreads();
        }
        if (t == TT) break;
        const int p = t & 1;

        // -------- phase A: prior, dy, features, a = relu(W1@kin + b1) --------
        if (tid < Mm) {
            float pr = 0.f;
            #pragma unroll
            for (int j = 0; j < Mm; j++) pr += F[tid * Mm + j] * s_post[j];
            s_prior[tid] = pr;
        }
        __syncthreads();
        if (tid < Nn) {
            float my = 0.f;
            #pragma unroll
            for (int j = 0; j < Mm; j++) my += Hm[tid * Mm + j] * s_prior[j];
            float yt = y[tid * TT + t];
            s_dy[tid]   = yt - my;
            s_diff[tid] = yt - s_yprev[tid];       // f1 raw
        }
        if (tid < Mm) {
            s_diff[10 + tid] = s_post[tid] - s_prevpost[tid];   // f3 raw
            s_diff[20 + tid] = s_post[tid] - s_prevprior[tid];  // f4 raw
        }
        __syncthreads();
        if (tid < 3) {
            float ss = 0.f;
            #pragma unroll
            for (int j = 0; j < 10; j++) { float d = s_diff[tid * 10 + j]; ss += d * d; }
            s_inv[tid] = 1.0f / fmaxf(sqrtf(ss), 1e-12f);
        }
        __syncthreads();
        if (tid < DIN) s_kin[tid] = s_diff[tid] * s_inv[tid / 10];
        __syncthreads();
        for (int r = gwarp; r < H1; r += NWRP) {
            float acc = (lane < DIN) ? W1[r * DIN + lane] * s_kin[lane] : 0.f;
            acc = wred(acc);
            if (lane == 0) g_a[r] = fmaxf(acc + b1[r], 0.0f);
        }
        grid_sync();

        // -------- phase B: GRU cell 0 --------
        gru_phase<H1>(Wi0, Wh0, bi0, bh0, g_a, g_h1[p], g_h1[p ^ 1], gwarp, lane);
        grid_sync();

        // -------- phase C: GRU cell 1 --------
        gru_phase<HID>(Wi1, Wh1, bi1, bh1, g_h1[p ^ 1], g_h2[p], g_h2[p ^ 1], gwarp, lane);
        grid_sync();

        // -------- phase D: g = relu(W2 @ h2n + b2) --------
        {
            const float4* h4 = (const float4*)(g_h2[p ^ 1]);
            for (int r = gwarp; r < H2; r += NWRP) {
                const float4* w4 = (const float4*)(W2 + (size_t)r * HID);
                float acc = 0.f;
                #pragma unroll 4
                for (int k = lane; k < HID / 4; k += 32) {
                    float4 w = w4[k], h = h4[k];
                    acc += w.x * h.x + w.y * h.y + w.z * h.z + w.w * h.w;
                }
                acc = wred(acc);
                if (lane == 0) g_g[r] = fmaxf(acc + b2[r], 0.0f);
            }
        }
        grid_sync();
    }
}

extern "C" void kernel_launch(void* const* d_in, const int* in_sizes, int n_in,
                              void* d_out, int out_size) {
    const float* y     = (const float*)d_in[0];
    const float* m1x_0 = (const float*)d_in[1];
    const float* F     = (const float*)d_in[2];
    const float* Hm    = (const float*)d_in[3];
    const float* h0    = (const float*)d_in[4];
    const float* W1    = (const float*)d_in[5];
    const float* b1    = (const float*)d_in[6];
    const float* Wi0   = (const float*)d_in[7];
    const float* Wh0   = (const float*)d_in[8];
    const float* bi0   = (const float*)d_in[9];
    const float* bh0   = (const float*)d_in[10];
    const float* Wi1   = (const float*)d_in[11];
    const float* Wh1   = (const float*)d_in[12];
    const float* bi1   = (const float*)d_in[13];
    const float* bh1   = (const float*)d_in[14];
    const float* W2    = (const float*)d_in[15];
    const float* b2    = (const float*)d_in[16];
    const float* W3    = (const float*)d_in[17];
    const float* b3    = (const float*)d_in[18];
    float* out = (float*)d_out;

    const size_t shmem = (size_t)DOUT * H2 * sizeof(float);  // 160 KB
    cudaFuncSetAttribute(knet_kernel,
                         cudaFuncAttributeMaxDynamicSharedMemorySize, (int)shmem);
    knet_kernel<<<NCTA, NTHR, shmem>>>(
        y, m1x_0, F, Hm, h0, W1, b1, Wi0, Wh0, bi0, bh0,
        Wi1, Wh1, bi1, bh1, W2, b2, W3, b3, out);
}

// round 7
// speedup vs baseline: 1.8789x; 1.8789x over previous
#include <cuda_runtime.h>
#include <cuda_fp16.h>
#include <math.h>

// ---------------- problem constants ----------------
#define NCTA 148
#define NTHR 512
#define WPC  16                 // warps per CTA
#define NWRP (NCTA * WPC)       // 2368 warps grid-wide

#define Mm   10
#define Nn   10
#define TT   100
#define H1   1600
#define H2   400
#define HID  2000
#define DIN  30
#define DOUT 100

// ---------------- global scratch (no allocation allowed) ----------------
__device__ float g_a[H1];
__device__ float g_h1[2][HID];
__device__ float g_h2[2][HID];
__device__ float g_g[H2];

// fp16 weight copies (converted every launch by convert_k). ~93 MB total,
// fits GB300's ~126 MB L2 -> the 100-step loop streams from L2, not DRAM.
__device__ __half c_Wi0[3 * HID * H1];    // 9.6M
__device__ __half c_Wh0[3 * HID * HID];   // 12M
__device__ __half c_Wi1[3 * HID * HID];   // 12M
__device__ __half c_Wh1[3 * HID * HID];   // 12M
__device__ __half c_W2[H2 * HID];         // 0.8M

// software grid barrier state
__device__ unsigned g_count;
__device__ volatile unsigned g_gen;

// 148 CTAs at 1 CTA/SM are co-resident on GB300's 152 SMs -> spin is safe.
__device__ __forceinline__ void grid_sync() {
    __threadfence();
    __syncthreads();
    if (threadIdx.x == 0) {
        unsigned gen = g_gen;
        if (atomicAdd(&g_count, 1u) == (unsigned)gridDim.x - 1u) {
            g_count = 0u;
            __threadfence();
            g_gen = gen + 1u;
        } else {
            while (g_gen == gen) { __nanosleep(32); }
        }
        __threadfence();
    }
    __syncthreads();
}

__device__ __forceinline__ float wred(float v) {
    v += __shfl_xor_sync(0xffffffffu, v, 16);
    v += __shfl_xor_sync(0xffffffffu, v, 8);
    v += __shfl_xor_sync(0xffffffffu, v, 4);
    v += __shfl_xor_sync(0xffffffffu, v, 2);
    v += __shfl_xor_sync(0xffffffffu, v, 1);
    return v;
}

__device__ __forceinline__ float sigmoidf_(float x) {
    return 1.0f / (1.0f + expf(-x));
}

// dot of 8 fp16 weights (packed in uint4) with 8 fp32 activations
__device__ __forceinline__ float dot8(uint4 w, float4 a, float4 b) {
    float2 p; float s;
    p = __half22float2(*(__half2*)&w.x); s  = p.x * a.x + p.y * a.y;
    p = __half22float2(*(__half2*)&w.y); s += p.x * a.z + p.y * a.w;
    p = __half22float2(*(__half2*)&w.z); s += p.x * b.x + p.y * b.y;
    p = __half22float2(*(__half2*)&w.w); s += p.x * b.z + p.y * b.w;
    return s;
}

// ---------------- fp32 -> fp16 conversion prologue ----------------
__device__ __forceinline__ void convert8(__half* dst, const float* src) {
    float4 a = *(const float4*)src;
    float4 b = *(const float4*)(src + 4);
    __half2 h0 = __floats2half2_rn(a.x, a.y);
    __half2 h1 = __floats2half2_rn(a.z, a.w);
    __half2 h2 = __floats2half2_rn(b.x, b.y);
    __half2 h3 = __floats2half2_rn(b.z, b.w);
    uint4 u;
    u.x = *(unsigned*)&h0; u.y = *(unsigned*)&h1;
    u.z = *(unsigned*)&h2; u.w = *(unsigned*)&h3;
    *(uint4*)dst = u;
}

__global__ void convert_k(const float* __restrict__ Wi0, const float* __restrict__ Wh0,
                          const float* __restrict__ Wi1, const float* __restrict__ Wh1,
                          const float* __restrict__ W2) {
    size_t stride = (size_t)gridDim.x * blockDim.x * 8;
    for (size_t i = ((size_t)blockIdx.x * blockDim.x + threadIdx.x) * 8;
         i < (size_t)3 * HID * HID; i += stride) {
        convert8(c_Wh0 + i, Wh0 + i);
        convert8(c_Wi1 + i, Wi1 + i);
        convert8(c_Wh1 + i, Wh1 + i);
        if (i < (size_t)3 * HID * H1) convert8(c_Wi0 + i, Wi0 + i);
        if (i < (size_t)H2 * HID)     convert8(c_W2 + i, W2 + i);
    }
}

// One GRU layer: warp-per-hidden-unit, fp16 weights, fp32 accumulate.
template<int KX>
__device__ __forceinline__ void gru_phase_h(
    const __half* __restrict__ Wi, const __half* __restrict__ Wh,
    const float* __restrict__ bi, const float* __restrict__ bh,
    const float* __restrict__ x,       // input, length KX (fp32)
    const float* __restrict__ hprev,   // length HID (fp32)
    float* __restrict__ hnew,          // length HID
    int gwarp, int lane)
{
    const float4* x4 = (const float4*)x;
    const float4* h4 = (const float4*)hprev;
    for (int j = gwarp; j < HID; j += NWRP) {
        float air = 0.f, aiz = 0.f, ain = 0.f;
        {
            const uint4* wir = (const uint4*)(Wi + (size_t)j * KX);
            const uint4* wiz = (const uint4*)(Wi + ((size_t)j + HID) * KX);
            const uint4* win = (const uint4*)(Wi + ((size_t)j + 2 * HID) * KX);
            #pragma unroll 2
            for (int k = lane; k < KX / 8; k += 32) {
                float4 xa = x4[2 * k], xb = x4[2 * k + 1];
                uint4 wr = wir[k], wz = wiz[k], wn = win[k];
                air += dot8(wr, xa, xb);
                aiz += dot8(wz, xa, xb);
                ain += dot8(wn, xa, xb);
            }
        }
        float ahr = 0.f, ahz = 0.f, ahn = 0.f;
        {
            const uint4* whr = (const uint4*)(Wh + (size_t)j * HID);
            const uint4* whz = (const uint4*)(Wh + ((size_t)j + HID) * HID);
            const uint4* whn = (const uint4*)(Wh + ((size_t)j + 2 * HID) * HID);
            #pragma unroll 2
            for (int k = lane; k < HID / 8; k += 32) {
                float4 ha = h4[2 * k], hb = h4[2 * k + 1];
                uint4 wr = whr[k], wz = whz[k], wn = whn[k];
                ahr += dot8(wr, ha, hb);
                ahz += dot8(wz, ha, hb);
                ahn += dot8(wn, ha, hb);
            }
        }
        air = wred(air); aiz = wred(aiz); ain = wred(ain);
        ahr = wred(ahr); ahz = wred(ahz); ahn = wred(ahn);

        if (lane == 0) {
            float rr = sigmoidf_(air + bi[j]          + ahr + bh[j]);
            float zz = sigmoidf_(aiz + bi[j + HID]    + ahz + bh[j + HID]);
            float nn = tanhf    (ain + bi[j + 2*HID]  + rr * (ahn + bh[j + 2*HID]));
            hnew[j] = (1.0f - zz) * nn + zz * hprev[j];
        }
    }
}

__global__ void __launch_bounds__(NTHR, 1) knet_kernel(
    const float* __restrict__ y,    const float* __restrict__ m1x_0,
    const float* __restrict__ F,    const float* __restrict__ Hm,
    const float* __restrict__ h0,
    const float* __restrict__ W1,   const float* __restrict__ b1,
    const float* __restrict__ bi0,  const float* __restrict__ bh0,
    const float* __restrict__ bi1,  const float* __restrict__ bh1,
    const float* __restrict__ b2,
    const float* __restrict__ W3,   const float* __restrict__ b3,
    float* __restrict__ out)
{
    __shared__ float s_post[Mm], s_prevpost[Mm], s_prevprior[Mm], s_yprev[Nn];
    __shared__ float s_prior[Mm], s_dy[Nn], s_np[Mm];
    __shared__ float s_diff[32], s_inv[4], s_kin[32];
    __shared__ float s_KG[DOUT];
    __shared__ float s_g[H2];
    extern __shared__ float W3s[];   // 100*400 floats = 160 KB, loaded once

    const int tid   = threadIdx.x;
    const int lane  = tid & 31;
    const int warp  = tid >> 5;
    const int gwarp = blockIdx.x * WPC + warp;
    const int gtid  = blockIdx.x * NTHR + tid;

    // ------------- init -------------
    for (int i = gtid; i < HID; i += NCTA * NTHR) {
        g_h1[0][i] = h0[i];
        g_h2[0][i] = h0[HID + i];
    }
    for (int i = tid; i < DOUT * H2; i += NTHR) W3s[i] = W3[i];
    if (tid < Mm) {
        float v = m1x_0[tid];
        s_post[tid] = v; s_prevpost[tid] = 0.0f; s_prevprior[tid] = v;
    }
    __syncthreads();
    if (tid < Mm) {   // tmp = F @ m1x_0
        float pr = 0.f;
        #pragma unroll
        for (int j = 0; j < Mm; j++) pr += F[tid * Mm + j] * s_post[j];
        s_prior[tid] = pr;
    }
    __syncthreads();
    if (tid < Nn) {   // y_prev0 = Hm @ tmp
        float v = 0.f;
        #pragma unroll
        for (int j = 0; j < Mm; j++) v += Hm[tid * Mm + j] * s_prior[j];
        s_yprev[tid] = v;
    }
    grid_sync();

    // ------------- time loop -------------
    for (int t = 0; t <= TT; t++) {
        if (t > 0) {
            // finalize prev step: KG = W3 @ g + b3, new_post = prior + KG @ dy
            for (int i = tid; i < H2; i += NTHR) s_g[i] = g_g[i];
            __syncthreads();
            for (int r = warp; r < DOUT; r += WPC) {
                float acc = 0.f;
                for (int k = lane; k < H2; k += 32) acc += W3s[r * H2 + k] * s_g[k];
                acc = wred(acc);
                if (lane == 0) s_KG[r] = acc + b3[r];
            }
            __syncthreads();
            if (tid < Mm) {
                float np = s_prior[tid];
                #pragma unroll
                for (int j = 0; j < Nn; j++) np += s_KG[tid * Nn + j] * s_dy[j];
                s_np[tid] = np;
                if (blockIdx.x == 0) out[tid * TT + (t - 1)] = np;
            }
            __syncthreads();
            if (tid < Mm) {
                s_prevpost[tid]  = s_post[tid];
                s_prevprior[tid] = s_prior[tid];
                s_post[tid]      = s_np[tid];
                s_yprev[tid]     = y[tid * TT + (t - 1)];
            }
            __syncthreads();
        }
        if (t == TT) break;
        const int p = t & 1;

        // -------- phase A: prior, dy, features, a = relu(W1@kin + b1) --------
        if (tid < Mm) {
            float pr = 0.f;
            #pragma unroll
            for (int j = 0; j < Mm; j++) pr += F[tid * Mm + j] * s_post[j];
            s_prior[tid] = pr;
        }
        __syncthreads();
        if (tid < Nn) {
            float my = 0.f;
            #pragma unroll
            for (int j = 0; j < Mm; j++) my += Hm[tid * Mm + j] * s_prior[j];
            float yt = y[tid * TT + t];
            s_dy[tid]   = yt - my;
            s_diff[tid] = yt - s_yprev[tid];
        }
        if (tid < Mm) {
            s_diff[10 + tid] = s_post[tid] - s_prevpost[tid];
            s_diff[20 + tid] = s_post[tid] - s_prevprior[tid];
        }
        __syncthreads();
        if (tid < 3) {
            float ss = 0.f;
            #pragma unroll
            for (int j = 0; j < 10; j++) { float d = s_diff[tid * 10 + j]; ss += d * d; }
            s_inv[tid] = 1.0f / fmaxf(sqrtf(ss), 1e-12f);
        }
        __syncthreads();
        if (tid < DIN) s_kin[tid] = s_diff[tid] * s_inv[tid / 10];
        __syncthreads();
        for (int r = gwarp; r < H1; r += NWRP) {
            float acc = (lane < DIN) ? W1[r * DIN + lane] * s_kin[lane] : 0.f;
            acc = wred(acc);
            if (lane == 0) g_a[r] = fmaxf(acc + b1[r], 0.0f);
        }
        grid_sync();

        // -------- phase B: GRU cell 0 --------
        gru_phase_h<H1>(c_Wi0, c_Wh0, bi0, bh0, g_a, g_h1[p], g_h1[p ^ 1], gwarp, lane);
        grid_sync();

        // -------- phase C: GRU cell 1 --------
        gru_phase_h<HID>(c_Wi1, c_Wh1, bi1, bh1, g_h1[p ^ 1], g_h2[p], g_h2[p ^ 1], gwarp, lane);
        grid_sync();

        // -------- phase D: g = relu(W2 @ h2n + b2) --------
        {
            const float4* h4 = (const float4*)(g_h2[p ^ 1]);
            for (int r = gwarp; r < H2; r += NWRP) {
                const uint4* w4 = (const uint4*)(c_W2 + (size_t)r * HID);
                float acc = 0.f;
                #pragma unroll 2
                for (int k = lane; k < HID / 8; k += 32) {
                    uint4 w = w4[k];
                    acc += dot8(w, h4[2 * k], h4[2 * k + 1]);
                }
                acc = wred(acc);
                if (lane == 0) g_g[r] = fmaxf(acc + b2[r], 0.0f);
            }
        }
        grid_sync();
    }
}

extern "C" void kernel_launch(void* const* d_in, const int* in_sizes, int n_in,
                              void* d_out, int out_size) {
    const float* y     = (const float*)d_in[0];
    const float* m1x_0 = (const float*)d_in[1];
    const float* F     = (const float*)d_in[2];
    const float* Hm    = (const float*)d_in[3];
    const float* h0    = (const float*)d_in[4];
    const float* W1    = (const float*)d_in[5];
    const float* b1    = (const float*)d_in[6];
    const float* Wi0   = (const float*)d_in[7];
    const float* Wh0   = (const float*)d_in[8];
    const float* bi0   = (const float*)d_in[9];
    const float* bh0   = (const float*)d_in[10];
    const float* Wi1   = (const float*)d_in[11];
    const float* Wh1   = (const float*)d_in[12];
    const float* bi1   = (const float*)d_in[13];
    const float* bh1   = (const float*)d_in[14];
    const float* W2    = (const float*)d_in[15];
    const float* b2    = (const float*)d_in[16];
    const float* W3    = (const float*)d_in[17];
    const float* b3    = (const float*)d_in[18];
    float* out = (float*)d_out;

    // prologue: fp32 -> fp16 weight conversion (graph-capturable, deterministic)
    convert_k<<<4096, 512>>>(Wi0, Wh0, Wi1, Wh1, W2);

    const size_t shmem = (size_t)DOUT * H2 * sizeof(float);  // 160 KB
    cudaFuncSetAttribute(knet_kernel,
                         cudaFuncAttributeMaxDynamicSharedMemorySize, (int)shmem);
    knet_kernel<<<NCTA, NTHR, shmem>>>(
        y, m1x_0, F, Hm, h0, W1, b1, bi0, bh0,
        bi1, bh1, b2, W3, b3, out);
}

// round 8
// speedup vs baseline: 1.9197x; 1.0217x over previous
#include <cuda_runtime.h>
#include <cuda_fp16.h>
#include <math.h>

// ---------------- problem constants ----------------
#define NCTA 148
#define NTHR 512
#define WPC  16                 // warps per CTA
#define NWRP (NCTA * WPC)       // 2368 warps grid-wide

#define Mm   10
#define Nn   10
#define TT   100
#define H1   1600
#define H2   400
#define HID  2000
#define DIN  30
#define DOUT 100

// ---------------- global scratch (no allocation allowed) ----------------
__device__ float g_a[H1];
__device__ float g_h1[2][HID];
__device__ float g_h2[2][HID];
__device__ float g_g[H2];

// fp16 weight copies (converted every launch by convert_k). ~93 MB total,
// fits GB300's ~126 MB L2 -> the 100-step loop streams from L2, not DRAM.
__device__ __half c_Wi0[3 * HID * H1];    // 9.6M
__device__ __half c_Wh0[3 * HID * HID];   // 12M
__device__ __half c_Wi1[3 * HID * HID];   // 12M
__device__ __half c_Wh1[3 * HID * HID];   // 12M
__device__ __half c_W2[H2 * HID];         // 0.8M

// software grid barrier state
__device__ unsigned g_count;
__device__ volatile unsigned g_gen;

// 148 CTAs at 1 CTA/SM are co-resident on GB300's 152 SMs -> spin is safe.
__device__ __forceinline__ void grid_sync() {
    __threadfence();
    __syncthreads();
    if (threadIdx.x == 0) {
        unsigned gen = g_gen;
        if (atomicAdd(&g_count, 1u) == (unsigned)gridDim.x - 1u) {
            g_count = 0u;
            __threadfence();
            g_gen = gen + 1u;
        } else {
            while (g_gen == gen) { __nanosleep(32); }
        }
        __threadfence();
    }
    __syncthreads();
}

__device__ __forceinline__ float wred(float v) {
    v += __shfl_xor_sync(0xffffffffu, v, 16);
    v += __shfl_xor_sync(0xffffffffu, v, 8);
    v += __shfl_xor_sync(0xffffffffu, v, 4);
    v += __shfl_xor_sync(0xffffffffu, v, 2);
    v += __shfl_xor_sync(0xffffffffu, v, 1);
    return v;
}

__device__ __forceinline__ float sigmoidf_(float x) {
    return 1.0f / (1.0f + expf(-x));
}

// dot of 8 fp16 weights (packed in uint4) with 8 fp32 activations
__device__ __forceinline__ float dot8(uint4 w, float4 a, float4 b) {
    float2 p; float s;
    p = __half22float2(*(__half2*)&w.x); s  = p.x * a.x + p.y * a.y;
    p = __half22float2(*(__half2*)&w.y); s += p.x * a.z + p.y * a.w;
    p = __half22float2(*(__half2*)&w.z); s += p.x * b.x + p.y * b.y;
    p = __half22float2(*(__half2*)&w.w); s += p.x * b.z + p.y * b.w;
    return s;
}

// ---------------- fp32 -> fp16 conversion prologue ----------------
__device__ __forceinline__ void convert8(__half* dst, const float* src) {
    float4 a = *(const float4*)src;
    float4 b = *(const float4*)(src + 4);
    __half2 h0 = __floats2half2_rn(a.x, a.y);
    __half2 h1 = __floats2half2_rn(a.z, a.w);
    __half2 h2 = __floats2half2_rn(b.x, b.y);
    __half2 h3 = __floats2half2_rn(b.z, b.w);
    uint4 u;
    u.x = *(unsigned*)&h0; u.y = *(unsigned*)&h1;
    u.z = *(unsigned*)&h2; u.w = *(unsigned*)&h3;
    *(uint4*)dst = u;
}

__global__ void convert_k(const float* __restrict__ Wi0, const float* __restrict__ Wh0,
                          const float* __restrict__ Wi1, const float* __restrict__ Wh1,
                          const float* __restrict__ W2) {
    size_t stride = (size_t)gridDim.x * blockDim.x * 8;
    for (size_t i = ((size_t)blockIdx.x * blockDim.x + threadIdx.x) * 8;
         i < (size_t)3 * HID * HID; i += stride) {
        convert8(c_Wh0 + i, Wh0 + i);
        convert8(c_Wi1 + i, Wi1 + i);
        convert8(c_Wh1 + i, Wh1 + i);
        if (i < (size_t)3 * HID * H1) convert8(c_Wi0 + i, Wi0 + i);
        if (i < (size_t)H2 * HID)     convert8(c_W2 + i, W2 + i);
    }
}

// One GRU layer: warp-per-hidden-unit, fp16 weights, fp32 accumulate.
// Wi and Wh dot products are FUSED into one loop so ~12 weight loads are in
// flight at once (vs ~6 with sequential loops) against L2 latency.
// KXU = KX/8 (uint4 units of the Wi row). HU = HID/8 for the Wh row.
template<int KXU>
__device__ __forceinline__ void gru_phase_h(
    const __half* __restrict__ Wi, const __half* __restrict__ Wh,
    const float* __restrict__ bi, const float* __restrict__ bh,
    const float* __restrict__ x,       // input, length KXU*8 (fp32)
    const float* __restrict__ hprev,   // length HID (fp32)
    float* __restrict__ hnew,          // length HID
    int gwarp, int lane)
{
    constexpr int KX = KXU * 8;
    constexpr int HU = HID / 8;        // 250
    const float4* x4 = (const float4*)x;
    const float4* h4 = (const float4*)hprev;
    int j = gwarp;                     // NWRP (2368) >= HID (2000): one unit max
    if (j < HID) {
        const uint4* wir = (const uint4*)(Wi + (size_t)j * KX);
        const uint4* wiz = (const uint4*)(Wi + ((size_t)j + HID) * KX);
        const uint4* win = (const uint4*)(Wi + ((size_t)j + 2 * HID) * KX);
        const uint4* whr = (const uint4*)(Wh + (size_t)j * HID);
        const uint4* whz = (const uint4*)(Wh + ((size_t)j + HID) * HID);
        const uint4* whn = (const uint4*)(Wh + ((size_t)j + 2 * HID) * HID);

        float air = 0.f, aiz = 0.f, ain = 0.f;
        float ahr = 0.f, ahz = 0.f, ahn = 0.f;
        #pragma unroll 2
        for (int k = lane; k < KXU; k += 32) {
            float4 xa = x4[2 * k], xb = x4[2 * k + 1];
            float4 ha = h4[2 * k], hb = h4[2 * k + 1];
            uint4 w0 = wir[k], w1 = wiz[k], w2 = win[k];
            uint4 v0 = whr[k], v1 = whz[k], v2 = whn[k];
            air += dot8(w0, xa, xb);
            aiz += dot8(w1, xa, xb);
            ain += dot8(w2, xa, xb);
            ahr += dot8(v0, ha, hb);
            ahz += dot8(v1, ha, hb);
            ahn += dot8(v2, ha, hb);
        }
        if constexpr (KXU < HU) {
            // Wh-only tail: indices [KXU, HU) covered exactly once across lanes.
            #pragma unroll 1
            for (int k = KXU + lane; k < HU; k += 32) {
                float4 ha = h4[2 * k], hb = h4[2 * k + 1];
                uint4 v0 = whr[k], v1 = whz[k], v2 = whn[k];
                ahr += dot8(v0, ha, hb);
                ahz += dot8(v1, ha, hb);
                ahn += dot8(v2, ha, hb);
            }
        }
        // 4 reductions instead of 6: r and z gates only need the sums.
        float rs = wred(air + ahr);
        float zs = wred(aiz + ahz);
        float ni = wred(ain);
        float nh = wred(ahn);

        if (lane == 0) {
            float rr = sigmoidf_(rs + bi[j]          + bh[j]);
            float zz = sigmoidf_(zs + bi[j + HID]    + bh[j + HID]);
            float nn = tanhf    (ni + bi[j + 2*HID]  + rr * (nh + bh[j + 2*HID]));
            hnew[j] = (1.0f - zz) * nn + zz * hprev[j];
        }
    }
}

__global__ void __launch_bounds__(NTHR, 1) knet_kernel(
    const float* __restrict__ y,    const float* __restrict__ m1x_0,
    const float* __restrict__ F,    const float* __restrict__ Hm,
    const float* __restrict__ h0,
    const float* __restrict__ W1,   const float* __restrict__ b1,
    const float* __restrict__ bi0,  const float* __restrict__ bh0,
    const float* __restrict__ bi1,  const float* __restrict__ bh1,
    const float* __restrict__ b2,
    const float* __restrict__ W3,   const float* __restrict__ b3,
    float* __restrict__ out)
{
    __shared__ float s_post[Mm], s_prevpost[Mm], s_prevprior[Mm], s_yprev[Nn];
    __shared__ float s_prior[Mm], s_dy[Nn], s_np[Mm];
    __shared__ float s_diff[32], s_inv[4], s_kin[32];
    __shared__ float s_KG[DOUT];
    __shared__ float s_g[H2];
    extern __shared__ float W3s[];   // 100*400 floats = 160 KB, loaded once

    const int tid   = threadIdx.x;
    const int lane  = tid & 31;
    const int warp  = tid >> 5;
    const int gwarp = blockIdx.x * WPC + warp;
    const int gtid  = blockIdx.x * NTHR + tid;

    // ------------- init -------------
    for (int i = gtid; i < HID; i += NCTA * NTHR) {
        g_h1[0][i] = h0[i];
        g_h2[0][i] = h0[HID + i];
    }
    for (int i = tid; i < DOUT * H2; i += NTHR) W3s[i] = W3[i];
    if (tid < Mm) {
        float v = m1x_0[tid];
        s_post[tid] = v; s_prevpost[tid] = 0.0f; s_prevprior[tid] = v;
    }
    __syncthreads();
    if (tid < Mm) {   // tmp = F @ m1x_0
        float pr = 0.f;
        #pragma unroll
        for (int j = 0; j < Mm; j++) pr += F[tid * Mm + j] * s_post[j];
        s_prior[tid] = pr;
    }
    __syncthreads();
    if (tid < Nn) {   // y_prev0 = Hm @ tmp
        float v = 0.f;
        #pragma unroll
        for (int j = 0; j < Mm; j++) v += Hm[tid * Mm + j] * s_prior[j];
        s_yprev[tid] = v;
    }
    grid_sync();

    // ------------- time loop -------------
    for (int t = 0; t <= TT; t++) {
        if (t > 0) {
            // finalize prev step: KG = W3 @ g + b3, new_post = prior + KG @ dy
            for (int i = tid; i < H2; i += NTHR) s_g[i] = g_g[i];
            __syncthreads();
            for (int r = warp; r < DOUT; r += WPC) {
                float acc = 0.f;
                for (int k = lane; k < H2; k += 32) acc += W3s[r * H2 + k] * s_g[k];
                acc = wred(acc);
                if (lane == 0) s_KG[r] = acc + b3[r];
            }
            __syncthreads();
            if (tid < Mm) {
                float np = s_prior[tid];
                #pragma unroll
                for (int j = 0; j < Nn; j++) np += s_KG[tid * Nn + j] * s_dy[j];
                s_np[tid] = np;
                if (blockIdx.x == 0) out[tid * TT + (t - 1)] = np;
            }
            __syncthreads();
            if (tid < Mm) {
                s_prevpost[tid]  = s_post[tid];
                s_prevprior[tid] = s_prior[tid];
                s_post[tid]      = s_np[tid];
                s_yprev[tid]     = y[tid * TT + (t - 1)];
            }
            __syncthreads();
        }
        if (t == TT) break;
        const int p = t & 1;

        // -------- phase A: prior, dy, features, a = relu(W1@kin + b1) --------
        if (tid < Mm) {
            float pr = 0.f;
            #pragma unroll
            for (int j = 0; j < Mm; j++) pr += F[tid * Mm + j] * s_post[j];
            s_prior[tid] = pr;
        }
        __syncthreads();
        if (tid < Nn) {
            float my = 0.f;
            #pragma unroll
            for (int j = 0; j < Mm; j++) my += Hm[tid * Mm + j] * s_prior[j];
            float yt = y[tid * TT + t];
            s_dy[tid]   = yt - my;
            s_diff[tid] = yt - s_yprev[tid];
        }
        if (tid < Mm) {
            s_diff[10 + tid] = s_post[tid] - s_prevpost[tid];
            s_diff[20 + tid] = s_post[tid] - s_prevprior[tid];
        }
        __syncthreads();
        if (tid < 3) {
            float ss = 0.f;
            #pragma unroll
            for (int j = 0; j < 10; j++) { float d = s_diff[tid * 10 + j]; ss += d * d; }
            s_inv[tid] = 1.0f / fmaxf(sqrtf(ss), 1e-12f);
        }
        __syncthreads();
        if (tid < DIN) s_kin[tid] = s_diff[tid] * s_inv[tid / 10];
        __syncthreads();
        for (int r = gwarp; r < H1; r += NWRP) {
            float acc = (lane < DIN) ? W1[r * DIN + lane] * s_kin[lane] : 0.f;
            acc = wred(acc);
            if (lane == 0) g_a[r] = fmaxf(acc + b1[r], 0.0f);
        }
        grid_sync();

        // -------- phase B: GRU cell 0 (KX = H1 = 1600 -> KXU = 200) --------
        gru_phase_h<H1 / 8>(c_Wi0, c_Wh0, bi0, bh0, g_a, g_h1[p], g_h1[p ^ 1], gwarp, lane);
        grid_sync();

        // -------- phase C: GRU cell 1 (KX = HID = 2000 -> KXU = 250) --------
        gru_phase_h<HID / 8>(c_Wi1, c_Wh1, bi1, bh1, g_h1[p ^ 1], g_h2[p], g_h2[p ^ 1], gwarp, lane);
        grid_sync();

        // -------- phase D: g = relu(W2 @ h2n + b2) --------
        {
            const float4* h4 = (const float4*)(g_h2[p ^ 1]);
            for (int r = gwarp; r < H2; r += NWRP) {
                const uint4* w4 = (const uint4*)(c_W2 + (size_t)r * HID);
                float acc = 0.f;
                #pragma unroll 2
                for (int k = lane; k < HID / 8; k += 32) {
                    uint4 w = w4[k];
                    acc += dot8(w, h4[2 * k], h4[2 * k + 1]);
                }
                acc = wred(acc);
                if (lane == 0) g_g[r] = fmaxf(acc + b2[r], 0.0f);
            }
        }
        grid_sync();
    }
}

extern "C" void kernel_launch(void* const* d_in, const int* in_sizes, int n_in,
                              void* d_out, int out_size) {
    const float* y     = (const float*)d_in[0];
    const float* m1x_0 = (const float*)d_in[1];
    const float* F     = (const float*)d_in[2];
    const float* Hm    = (const float*)d_in[3];
    const float* h0    = (const float*)d_in[4];
    const float* W1    = (const float*)d_in[5];
    const float* b1    = (const float*)d_in[6];
    const float* Wi0   = (const float*)d_in[7];
    const float* Wh0   = (const float*)d_in[8];
    const float* bi0   = (const float*)d_in[9];
    const float* bh0   = (const float*)d_in[10];
    const float* Wi1   = (const float*)d_in[11];
    const float* Wh1   = (const float*)d_in[12];
    const float* bi1   = (const float*)d_in[13];
    const float* bh1   = (const float*)d_in[14];
    const float* W2    = (const float*)d_in[15];
    const float* b2    = (const float*)d_in[16];
    const float* W3    = (const float*)d_in[17];
    const float* b3    = (const float*)d_in[18];
    float* out = (float*)d_out;

    // prologue: fp32 -> fp16 weight conversion (graph-capturable, deterministic)
    convert_k<<<4096, 512>>>(Wi0, Wh0, Wi1, Wh1, W2);

    const size_t shmem = (size_t)DOUT * H2 * sizeof(float);  // 160 KB
    cudaFuncSetAttribute(knet_kernel,
                         cudaFuncAttributeMaxDynamicSharedMemorySize, (int)shmem);
    knet_kernel<<<NCTA, NTHR, shmem>>>(
        y, m1x_0, F, Hm, h0, W1, b1, bi0, bh0,
        bi1, bh1, b2, W3, b3, out);
}